// round 2
// baseline (speedup 1.0000x reference)
#include <cuda_runtime.h>
#include <cuda_bf16.h>

// LSTM autoencoder, B independent sequences.
// Restructured for low register pressure: gates processed per unit-pair
// (only 4 packed accumulators live), hidden state kept pre-packed {h,h}
// with ping-pong buffers, weights re-laid-out in shared as [pair][k][8].

#define UNITS 10
#define TIN   50
#define TOUT  3
#define BLK   128
#define CH    10   // input staging chunk (time steps)

typedef unsigned long long ull;

__device__ __forceinline__ ull fma2(ull a, ull b, ull c) {
    ull d;
    asm("fma.rn.f32x2 %0, %1, %2, %3;" : "=l"(d) : "l"(a), "l"(b), "l"(c));
    return d;
}
__device__ __forceinline__ ull pack2(float x) {
    ull d;
    asm("mov.b64 %0, {%1, %1};" : "=l"(d) : "f"(x));
    return d;
}
__device__ __forceinline__ float2 unpack2(ull v) {
    float2 r;
    asm("mov.b64 {%0, %1}, %2;" : "=f"(r.x), "=f"(r.y) : "l"(v));
    return r;
}
// sigmoid via ex2 + rcp (2 MUFU, ~ulp accurate)
__device__ __forceinline__ float sigmoidf_(float x) {
    float e, r;
    asm("ex2.approx.f32 %0, %1;" : "=f"(e) : "f"(x * -1.4426950408889634f));
    asm("rcp.approx.f32 %0, %1;" : "=f"(r) : "f"(e + 1.0f));
    return r;
}

// Gate math for unit pair p from 4 packed accumulators; writes packed h.
__device__ __forceinline__ void gates2(ull z0, ull z1, ull z2, ull z3,
                                       float* __restrict__ c,
                                       ull* __restrict__ hout, int p) {
    float2 zi = unpack2(z0), zf = unpack2(z1), zg = unpack2(z2), zo = unpack2(z3);
    int u = 2 * p;
    {
        float i_ = sigmoidf_(zi.x), f_ = sigmoidf_(zf.x);
        float g_ = fmaxf(zg.x, 0.0f), o_ = sigmoidf_(zo.x);
        float cv = f_ * c[u] + i_ * g_;
        c[u] = cv;
        hout[u] = pack2(o_ * fmaxf(cv, 0.0f));
    }
    {
        float i_ = sigmoidf_(zi.y), f_ = sigmoidf_(zf.y);
        float g_ = fmaxf(zg.y, 0.0f), o_ = sigmoidf_(zo.y);
        float cv = f_ * c[u + 1] + i_ * g_;
        c[u + 1] = cv;
        hout[u + 1] = pack2(o_ * fmaxf(cv, 0.0f));
    }
}

// One LSTM1 step: scalar input x, packed hidden hin -> hout.
__device__ __forceinline__ void lstm1_step(float x,
    const float* __restrict__ sW1p, const float* __restrict__ sb1p,
    const float* __restrict__ sG1,
    const ull* __restrict__ hin, ull* __restrict__ hout, float* __restrict__ c)
{
    ull xx = pack2(x);
#pragma unroll
    for (int p = 0; p < 5; p++) {
        const ulonglong2* wb = (const ulonglong2*)(sW1p + p * 8);
        const ulonglong2* bb = (const ulonglong2*)(sb1p + p * 8);
        ulonglong2 w0 = wb[0], w1 = wb[1];
        ulonglong2 b0 = bb[0], b1 = bb[1];
        ull z0 = fma2(xx, w0.x, b0.x);
        ull z1 = fma2(xx, w0.y, b0.y);
        ull z2 = fma2(xx, w1.x, b1.x);
        ull z3 = fma2(xx, w1.y, b1.y);
        const ulonglong2* Rv = (const ulonglong2*)(sG1 + p * 80);
#pragma unroll
        for (int k = 0; k < 10; k++) {
            ulonglong2 wa = Rv[2 * k], wc = Rv[2 * k + 1];
            ull hh = hin[k];
            z0 = fma2(hh, wa.x, z0);
            z1 = fma2(hh, wa.y, z1);
            z2 = fma2(hh, wc.x, z2);
            z3 = fma2(hh, wc.y, z3);
        }
        gates2(z0, z1, z2, z3, c, hout, p);
    }
}

// One LSTM2 step: constant input vector h1 (packed), recurrent hin -> hout.
// Fuses the Dense(10->1) projection; returns the dense output.
__device__ __forceinline__ float lstm2_step(
    const ull* __restrict__ h1, const ull* __restrict__ hin,
    ull* __restrict__ hout, float* __restrict__ c,
    const float* __restrict__ sGW2, const float* __restrict__ sGR2,
    const float* __restrict__ sb2p, const float* __restrict__ sWd, float bd0)
{
    float acc = bd0;
#pragma unroll
    for (int p = 0; p < 5; p++) {
        const ulonglong2* bb = (const ulonglong2*)(sb2p + p * 8);
        ulonglong2 b0 = bb[0], b1 = bb[1];
        ull z0 = b0.x, z1 = b0.y, z2 = b1.x, z3 = b1.y;
        const ulonglong2* Wv = (const ulonglong2*)(sGW2 + p * 80);
#pragma unroll
        for (int k = 0; k < 10; k++) {
            ulonglong2 wa = Wv[2 * k], wc = Wv[2 * k + 1];
            ull hh = h1[k];
            z0 = fma2(hh, wa.x, z0);
            z1 = fma2(hh, wa.y, z1);
            z2 = fma2(hh, wc.x, z2);
            z3 = fma2(hh, wc.y, z3);
        }
        const ulonglong2* Rv = (const ulonglong2*)(sGR2 + p * 80);
#pragma unroll
        for (int k = 0; k < 10; k++) {
            ulonglong2 wa = Rv[2 * k], wc = Rv[2 * k + 1];
            ull hh = hin[k];
            z0 = fma2(hh, wa.x, z0);
            z1 = fma2(hh, wa.y, z1);
            z2 = fma2(hh, wc.x, z2);
            z3 = fma2(hh, wc.y, z3);
        }
        // gates + fused dense
        float2 zi = unpack2(z0), zf = unpack2(z1), zg = unpack2(z2), zo = unpack2(z3);
        int u = 2 * p;
        {
            float i_ = sigmoidf_(zi.x), f_ = sigmoidf_(zf.x);
            float g_ = fmaxf(zg.x, 0.0f), o_ = sigmoidf_(zo.x);
            float cv = f_ * c[u] + i_ * g_;
            c[u] = cv;
            float hv = o_ * fmaxf(cv, 0.0f);
            hout[u] = pack2(hv);
            acc = fmaf(hv, sWd[u], acc);
        }
        {
            float i_ = sigmoidf_(zi.y), f_ = sigmoidf_(zf.y);
            float g_ = fmaxf(zg.y, 0.0f), o_ = sigmoidf_(zo.y);
            float cv = f_ * c[u + 1] + i_ * g_;
            c[u + 1] = cv;
            float hv = o_ * fmaxf(cv, 0.0f);
            hout[u + 1] = pack2(hv);
            acc = fmaf(hv, sWd[u + 1], acc);
        }
    }
    return acc;
}

__global__ __launch_bounds__(BLK, 5) void lstm_ae_kernel(
    const float* __restrict__ inputs,
    const float* __restrict__ W1, const float* __restrict__ R1, const float* __restrict__ b1,
    const float* __restrict__ W2, const float* __restrict__ R2, const float* __restrict__ b2,
    const float* __restrict__ Wd, const float* __restrict__ bd,
    float* __restrict__ out, int B)
{
    // weights re-laid out as [pair p][k][8]: (i_lo,i_hi,f_lo,f_hi,g_lo,g_hi,o_lo,o_hi)
    __shared__ __align__(16) float sG1[400];
    __shared__ __align__(16) float sGR2[400];
    __shared__ __align__(16) float sGW2[400];
    __shared__ __align__(16) float sW1p[40];
    __shared__ __align__(16) float sb1p[40];
    __shared__ __align__(16) float sb2p[40];
    __shared__ float sWd[UNITS];
    __shared__ float sbd;
    __shared__ float xs[CH][BLK + 1];   // staged inputs, transposed

    const int tid  = threadIdx.x;
    const int base = blockIdx.x * BLK;

    // --- weight re-layout into shared ---
    for (int i = tid; i < 400; i += BLK) {
        int p = i / 80;
        int r = i - p * 80;
        int k = r >> 3;
        int j = r & 7;
        int col = (j >> 1) * 10 + 2 * p + (j & 1);
        int src = k * 40 + col;
        sG1[i]  = R1[src];
        sGR2[i] = R2[src];
        sGW2[i] = W2[src];
    }
    if (tid < 40) {
        int p = tid >> 3;
        int j = tid & 7;
        int col = (j >> 1) * 10 + 2 * p + (j & 1);
        sW1p[tid] = W1[col];
        sb1p[tid] = b1[col];
        sb2p[tid] = b2[col];
    }
    if (tid < UNITS) sWd[tid] = Wd[tid];
    if (tid == 0)    sbd = bd[0];

    const long gbase = (long)base * TIN;
    const long total = (long)B * TIN;

    ull   hA[UNITS], hB[UNITS];
    float c[UNITS];
    ull zero = pack2(0.0f);
#pragma unroll
    for (int u = 0; u < UNITS; u++) { hA[u] = zero; c[u] = 0.0f; }

    // ================= LSTM 1: 50 steps in 5 chunks of 10 =================
    for (int t0 = 0; t0 < TIN; t0 += CH) {
        __syncthreads();
        for (int idx = tid; idx < CH * BLK; idx += BLK) {
            int e = idx / CH;
            int t = idx - e * CH;
            long g = gbase + (long)e * TIN + t0 + t;
            xs[t][e] = (g < total) ? inputs[g] : 0.0f;
        }
        __syncthreads();
#pragma unroll
        for (int t = 0; t < CH; t += 2) {
            lstm1_step(xs[t][tid],     sW1p, sb1p, sG1, hA, hB, c);
            lstm1_step(xs[t + 1][tid], sW1p, sb1p, sG1, hB, hA, c);
        }
    }
    // 50 steps (even) -> final h1 is in hA

    // ================= LSTM 2 (3 steps) + fused Dense =================
    ull h2a[UNITS], h2b[UNITS];
    float c2[UNITS];
#pragma unroll
    for (int u = 0; u < UNITS; u++) { h2a[u] = zero; c2[u] = 0.0f; }

    const int  elem  = base + tid;
    const bool valid = elem < B;
    float bd0 = sbd;

    float o0 = lstm2_step(hA, h2a, h2b, c2, sGW2, sGR2, sb2p, sWd, bd0);
    float o1 = lstm2_step(hA, h2b, h2a, c2, sGW2, sGR2, sb2p, sWd, bd0);
    float o2 = lstm2_step(hA, h2a, h2b, c2, sGW2, sGR2, sb2p, sWd, bd0);

    if (valid) {
        float* po = out + (long)elem * TOUT;
        po[0] = o0;
        po[1] = o1;
        po[2] = o2;
    }
}

extern "C" void kernel_launch(void* const* d_in, const int* in_sizes, int n_in,
                              void* d_out, int out_size) {
    const float* inputs = (const float*)d_in[0];
    const float* W1     = (const float*)d_in[1];
    const float* R1     = (const float*)d_in[2];
    const float* b1     = (const float*)d_in[3];
    const float* W2     = (const float*)d_in[4];
    const float* R2     = (const float*)d_in[5];
    const float* b2     = (const float*)d_in[6];
    const float* Wd     = (const float*)d_in[7];
    const float* bd     = (const float*)d_in[8];
    float* out = (float*)d_out;

    int B = in_sizes[0] / TIN;
    int grid = (B + BLK - 1) / BLK;
    lstm_ae_kernel<<<grid, BLK>>>(inputs, W1, R1, b1, W2, R2, b2, Wd, bd, out, B);
}